// round 1
// baseline (speedup 1.0000x reference)
#include <cuda_runtime.h>
#include <math.h>

// Shapes (fixed by the problem): B*N=6400 rows, K=1024 noise, D=64, V=1e6.
#define K_NOISE   1024
#define DIM       64
#define TILE_C    128     // noise columns per smem tile
#define R_BLK     16      // rows per block
#define THREADS_B 128

// Scratch (device globals — allocation-free per harness rules)
__device__ float g_noise[K_NOISE * DIM];   // gathered noise embeddings [K][D]
__device__ float g_c[K_NOISE];             // per-noise constant: NORM + q_k + LOG_K

// ---------------------------------------------------------------------------
// Kernel A: gather noise embedding rows + per-noise constants; zero d_out.
// ---------------------------------------------------------------------------
__global__ void gather_kernel(const int* __restrict__ noise_samples,
                              const float* __restrict__ embs,
                              const float* __restrict__ logprob_noise,
                              float norm_term, float log_k,
                              float* __restrict__ d_out)
{
    int k = blockIdx.x * blockDim.x + threadIdx.x;
    if (k == 0) d_out[0] = 0.0f;
    if (k < K_NOISE) {
        int row = noise_samples[k];
        const float4* src = (const float4*)(embs + (size_t)row * DIM);
        float4* dst = (float4*)(g_noise + (size_t)k * DIM);
#pragma unroll
        for (int i = 0; i < DIM / 4; i++) dst[i] = src[i];
        g_c[k] = norm_term + logprob_noise[row] + log_k;
    }
}

// ---------------------------------------------------------------------------
// softplus(x) = log(1 + e^x), robust across the full range, fast-math MUFU.
//   x > 8        : x + e^{-x}                      (err < e^{-16}/2)
//   e^x < 1/64   : z - z^2/2 + z^3/3               (err < z^4/4 ~ 1.5e-8)
//   else         : log(1 + e^x)
// ---------------------------------------------------------------------------
__device__ __forceinline__ float softplus_f(float x)
{
    if (x > 8.0f) return x + __expf(-x);
    float z = __expf(x);
    if (z < 0.015625f) return z * fmaf(z, fmaf(z, 0.33333334f, -0.5f), 1.0f);
    return __logf(1.0f + z);
}

// ---------------------------------------------------------------------------
// Kernel B: fused NCE loss.
//   Each block: 16 rows of `input`, all 1024 noise cols (tiled 128 into smem),
//   plus the 16 target-score terms. 4x4 register tile per thread.
//   Output: atomicAdd of block partial mean into d_out[0].
// ---------------------------------------------------------------------------
__global__ void __launch_bounds__(THREADS_B)
nce_kernel(const int* __restrict__ target,
           const float* __restrict__ input,
           const float* __restrict__ embs,
           const float* __restrict__ logprob_noise,
           float norm_term, float log_k, float inv_rows,
           float* __restrict__ d_out)
{
    __shared__ float  s_in[R_BLK][DIM];          // 4 KB  (broadcast reads)
    __shared__ float4 s_ns4[TILE_C * 17];        // 34 KB (64 floats padded to 68: odd f4 stride)
    __shared__ float  s_c[TILE_C];
    __shared__ float  s_red[THREADS_B / 32];

    const int tid  = threadIdx.x;
    const int lane = tid & 31;
    const int warp = tid >> 5;                    // row-group 0..3
    const int r0   = blockIdx.x * R_BLK;

    // --- load 16 input rows to smem (coalesced float4) ---
    {
        const float4* src = (const float4*)(input + (size_t)r0 * DIM);
        float4* dst = (float4*)(&s_in[0][0]);
#pragma unroll
        for (int i = 0; i < (R_BLK * DIM / 4) / THREADS_B; i++)
            dst[i * THREADS_B + tid] = src[i * THREADS_B + tid];
    }
    __syncthreads();

    float local = 0.0f;

    // --- target term: one thread per row (16 threads) ---
    if (tid < R_BLK) {
        int r = r0 + tid;
        int t = target[r];
        const float4* te = (const float4*)(embs + (size_t)t * DIM);
        float acc = 0.0f;
#pragma unroll
        for (int i = 0; i < DIM / 4; i++) {
            float4 e = te[i];
            acc = fmaf(e.x, s_in[tid][4 * i + 0],
                  fmaf(e.y, s_in[tid][4 * i + 1],
                  fmaf(e.z, s_in[tid][4 * i + 2],
                  fmaf(e.w, s_in[tid][4 * i + 3], acc))));
        }
        float xt = acc - norm_term - logprob_noise[t] - log_k;
        local += softplus_f(-xt);
    }

    // --- main loop over noise tiles ---
    for (int ct = 0; ct < K_NOISE / TILE_C; ct++) {
        __syncthreads();   // protect smem reuse from previous tile's readers
        // load noise tile: 128 cols x 16 f4 = 2048 f4, 16 per thread, coalesced in gmem
        {
            const float4* src = (const float4*)(g_noise + (size_t)ct * TILE_C * DIM);
#pragma unroll
            for (int i = 0; i < (TILE_C * DIM / 4) / THREADS_B; i++) {
                int flat = i * THREADS_B + tid;      // 0..2047
                int col  = flat >> 4;
                int d4   = flat & 15;
                s_ns4[col * 17 + d4] = src[flat];
            }
            s_c[tid] = g_c[ct * TILE_C + tid];       // THREADS_B == TILE_C
        }
        __syncthreads();

        float acc[4][4] = {};
#pragma unroll
        for (int d4 = 0; d4 < DIM / 4; d4++) {
            float4 a[4], b[4];
#pragma unroll
            for (int r = 0; r < 4; r++)              // broadcast (uniform per warp)
                a[r] = ((const float4*)&s_in[warp * 4 + r][0])[d4];
#pragma unroll
            for (int c = 0; c < 4; c++)              // odd stride 17 -> conflict-free
                b[c] = s_ns4[(c * 32 + lane) * 17 + d4];
#pragma unroll
            for (int r = 0; r < 4; r++)
#pragma unroll
                for (int c = 0; c < 4; c++)
                    acc[r][c] = fmaf(a[r].x, b[c].x,
                                fmaf(a[r].y, b[c].y,
                                fmaf(a[r].z, b[c].z,
                                fmaf(a[r].w, b[c].w, acc[r][c]))));
        }

        // epilogue: softplus of (score - c_k), accumulate
#pragma unroll
        for (int c = 0; c < 4; c++) {
            float ck = s_c[c * 32 + lane];
#pragma unroll
            for (int r = 0; r < 4; r++)
                local += softplus_f(acc[r][c] - ck);
        }
    }

    // --- block reduction + global atomic ---
#pragma unroll
    for (int o = 16; o; o >>= 1)
        local += __shfl_xor_sync(0xffffffffu, local, o);
    if (lane == 0) s_red[warp] = local;
    __syncthreads();
    if (tid == 0) {
        float s = (s_red[0] + s_red[1] + s_red[2] + s_red[3]) * inv_rows;
        atomicAdd(d_out, s);
    }
}

// ---------------------------------------------------------------------------
// Launch. Inputs (metadata order): target i32[6400], input f32[6400*64],
// embs f32[1e6*64], noise_samples i32[1024], logprob_noise f32[1e6].
// Output: f32[1] (mean loss).
// ---------------------------------------------------------------------------
extern "C" void kernel_launch(void* const* d_in, const int* in_sizes, int n_in,
                              void* d_out, int out_size)
{
    const int*   target = (const int*)d_in[0];
    const float* input  = (const float*)d_in[1];
    const float* embs   = (const float*)d_in[2];
    const int*   noise  = (const int*)d_in[3];
    const float* lpn    = (const float*)d_in[4];
    float*       out    = (float*)d_out;

    const int rows = in_sizes[0];                  // B*N = 6400
    const float norm_term = logf((float)in_sizes[4]);   // log(V)
    const float log_k     = logf((float)in_sizes[3]);   // log(K)

    gather_kernel<<<(K_NOISE + 127) / 128, 128>>>(noise, embs, lpn, norm_term, log_k, out);
    nce_kernel<<<rows / R_BLK, THREADS_B>>>(target, input, embs, lpn,
                                            norm_term, log_k, 1.0f / (float)rows, out);
}

// round 2
// speedup vs baseline: 1.0985x; 1.0985x over previous
#include <cuda_runtime.h>
#include <math.h>

// Shapes (fixed): B*N=6400 rows, K=1024 noise, D=64, V=1e6.
#define K_NOISE   1024
#define DIM       64
#define TILE_C    128     // noise columns per smem tile
#define R_BLK     16      // rows per block
#define THREADS_B 128
#define KSPLIT    2       // grid.y splits over the noise dimension

// Scratch (device globals — allocation-free per harness rules)
__device__ float g_noise[K_NOISE * DIM];   // gathered noise embeddings [K][D]
__device__ float g_c[K_NOISE];             // per-noise constant: NORM + q_k + LOG_K

typedef unsigned long long u64;

// packed f32x2 fused multiply-add (2 fp32 FMA per instruction; Blackwell FFMA2)
__device__ __forceinline__ u64 ffma2(u64 a, u64 b, u64 c)
{
    u64 d;
    asm("fma.rn.f32x2 %0, %1, %2, %3;" : "=l"(d) : "l"(a), "l"(b), "l"(c));
    return d;
}

__device__ __forceinline__ float f32x2_hsum(u64 v)
{
    float2 f = *(float2*)&v;
    return f.x + f.y;
}

// ---------------------------------------------------------------------------
// Kernel A: gather noise embedding rows + per-noise constants; zero d_out.
// ---------------------------------------------------------------------------
__global__ void gather_kernel(const int* __restrict__ noise_samples,
                              const float* __restrict__ embs,
                              const float* __restrict__ logprob_noise,
                              float norm_term, float log_k,
                              float* __restrict__ d_out)
{
    int k = blockIdx.x * blockDim.x + threadIdx.x;
    if (k == 0) d_out[0] = 0.0f;
    if (k < K_NOISE) {
        int row = noise_samples[k];
        const float4* src = (const float4*)(embs + (size_t)row * DIM);
        float4* dst = (float4*)(g_noise + (size_t)k * DIM);
#pragma unroll
        for (int i = 0; i < DIM / 4; i++) dst[i] = src[i];
        g_c[k] = norm_term + logprob_noise[row] + log_k;
    }
}

// ---------------------------------------------------------------------------
// softplus(x) = log(1 + e^x); noise path almost always takes the polynomial
// branch (z = e^x ~ 1e-3), so the common cost is 1 MUFU + 3 FMA.
// ---------------------------------------------------------------------------
__device__ __forceinline__ float softplus_f(float x)
{
    if (x > 8.0f) return x + __expf(-x);
    float z = __expf(x);
    if (z < 0.015625f) return z * fmaf(z, fmaf(z, 0.33333334f, -0.5f), 1.0f);
    return __logf(1.0f + z);
}

// ---------------------------------------------------------------------------
// Kernel B: fused NCE loss (split-K over noise dimension).
//   Block = 16 rows x (K_NOISE/KSPLIT) noise cols, tiled TILE_C into smem.
//   4 warps, each warp: 4 rows x 32 cols, 4x4 register tile per thread,
//   accumulation in packed f32x2 (even/odd d lanes).
// ---------------------------------------------------------------------------
__global__ void __launch_bounds__(THREADS_B, 5)
nce_kernel(const int* __restrict__ target,
           const float* __restrict__ input,
           const float* __restrict__ embs,
           const float* __restrict__ logprob_noise,
           float norm_term, float log_k, float inv_rows,
           float* __restrict__ d_out)
{
    __shared__ float  s_in[R_BLK][DIM];          // 4 KB  (broadcast reads)
    __shared__ float4 s_ns4[TILE_C * 17];        // ~34.8 KB (pad 16->17 f4: conflict-free)
    __shared__ float  s_c[TILE_C];
    __shared__ float  s_red[THREADS_B / 32];

    const int tid  = threadIdx.x;
    const int lane = tid & 31;
    const int warp = tid >> 5;                    // row-group 0..3
    const int r0   = blockIdx.x * R_BLK;
    const int ct0  = blockIdx.y * (K_NOISE / TILE_C / KSPLIT);

    // --- load 16 input rows to smem (coalesced float4) ---
    {
        const float4* src = (const float4*)(input + (size_t)r0 * DIM);
        float4* dst = (float4*)(&s_in[0][0]);
#pragma unroll
        for (int i = 0; i < (R_BLK * DIM / 4) / THREADS_B; i++)
            dst[i * THREADS_B + tid] = src[i * THREADS_B + tid];
    }
    __syncthreads();

    float local = 0.0f;

    // --- target term: only in split 0, one thread per row ---
    if (blockIdx.y == 0 && tid < R_BLK) {
        int r = r0 + tid;
        int t = target[r];
        const float4* te = (const float4*)(embs + (size_t)t * DIM);
        float acc = 0.0f;
#pragma unroll
        for (int i = 0; i < DIM / 4; i++) {
            float4 e = te[i];
            acc = fmaf(e.x, s_in[tid][4 * i + 0],
                  fmaf(e.y, s_in[tid][4 * i + 1],
                  fmaf(e.z, s_in[tid][4 * i + 2],
                  fmaf(e.w, s_in[tid][4 * i + 3], acc))));
        }
        float xt = acc - norm_term - logprob_noise[t] - log_k;
        local += softplus_f(-xt);
    }

    // --- main loop over this split's noise tiles ---
#pragma unroll
    for (int cti = 0; cti < K_NOISE / TILE_C / KSPLIT; cti++) {
        const int ct = ct0 + cti;
        __syncthreads();   // protect smem reuse from previous tile's readers
        {
            const float4* src = (const float4*)(g_noise + (size_t)ct * TILE_C * DIM);
#pragma unroll
            for (int i = 0; i < (TILE_C * DIM / 4) / THREADS_B; i++) {
                int flat = i * THREADS_B + tid;      // 0..2047
                int col  = flat >> 4;
                int d4   = flat & 15;
                s_ns4[col * 17 + d4] = src[flat];
            }
            s_c[tid] = g_c[ct * TILE_C + tid];       // THREADS_B == TILE_C
        }
        __syncthreads();

        u64 acc2[4][4] = {};                          // packed (even-d, odd-d) partials
#pragma unroll
        for (int d4 = 0; d4 < DIM / 4; d4++) {
            ulonglong2 a[4], b[4];
#pragma unroll
            for (int r = 0; r < 4; r++)               // broadcast (uniform per warp)
                a[r] = ((const ulonglong2*)&s_in[warp * 4 + r][0])[d4];
#pragma unroll
            for (int c = 0; c < 4; c++)               // odd stride 17 -> conflict-free
                b[c] = *(const ulonglong2*)&s_ns4[(c * 32 + lane) * 17 + d4];
#pragma unroll
            for (int r = 0; r < 4; r++)
#pragma unroll
                for (int c = 0; c < 4; c++) {
                    acc2[r][c] = ffma2(a[r].x, b[c].x, acc2[r][c]);
                    acc2[r][c] = ffma2(a[r].y, b[c].y, acc2[r][c]);
                }
        }

        // epilogue: softplus of (score - c_k), accumulate
#pragma unroll
        for (int c = 0; c < 4; c++) {
            float ck = s_c[c * 32 + lane];
#pragma unroll
            for (int r = 0; r < 4; r++)
                local += softplus_f(f32x2_hsum(acc2[r][c]) - ck);
        }
    }

    // --- block reduction + global atomic ---
#pragma unroll
    for (int o = 16; o; o >>= 1)
        local += __shfl_xor_sync(0xffffffffu, local, o);
    if (lane == 0) s_red[warp] = local;
    __syncthreads();
    if (tid == 0) {
        float s = (s_red[0] + s_red[1] + s_red[2] + s_red[3]) * inv_rows;
        atomicAdd(d_out, s);
    }
}

// ---------------------------------------------------------------------------
// Launch. Inputs (metadata order): target i32[6400], input f32[6400*64],
// embs f32[1e6*64], noise_samples i32[1024], logprob_noise f32[1e6].
// Output: f32[1] (mean loss).
// ---------------------------------------------------------------------------
extern "C" void kernel_launch(void* const* d_in, const int* in_sizes, int n_in,
                              void* d_out, int out_size)
{
    const int*   target = (const int*)d_in[0];
    const float* input  = (const float*)d_in[1];
    const float* embs   = (const float*)d_in[2];
    const int*   noise  = (const int*)d_in[3];
    const float* lpn    = (const float*)d_in[4];
    float*       out    = (float*)d_out;

    const int rows = in_sizes[0];                        // B*N = 6400
    const float norm_term = logf((float)in_sizes[4]);    // log(V)
    const float log_k     = logf((float)in_sizes[3]);    // log(K)

    gather_kernel<<<(K_NOISE + 127) / 128, 128>>>(noise, embs, lpn, norm_term, log_k, out);
    dim3 grid(rows / R_BLK, KSPLIT);
    nce_kernel<<<grid, THREADS_B>>>(target, input, embs, lpn,
                                    norm_term, log_k, 1.0f / (float)rows, out);
}

// round 4
// speedup vs baseline: 2.5279x; 2.3012x over previous
#include <cuda_runtime.h>
#include <cuda_bf16.h>
#include <math.h>
#include <stdint.h>

// Shapes (fixed): B*N=6400 rows, K=1024 noise, D=64, V=1e6.
#define DIM        64
#define K_NOISE    1024
#define ROWS_TOT   6400
#define MT         128                 // M tile (rows per CTA)
#define NT         128                 // N tile (noise cols per CTA)
#define TILE_BYTES (128 * 128)         // 128 rows x 128B (64 bf16) per tile

#define SW128(o) ((o) ^ (((o) >> 3) & 0x70))

// Device-global scratch (allocation-free): bf16 operands pre-swizzled into
// SW128 128-row tiles, plus per-noise constants.
__device__ __align__(16) __nv_bfloat16 g_in_bf16[ROWS_TOT * DIM];
__device__ __align__(16) __nv_bfloat16 g_noise_bf16[K_NOISE * DIM];
__device__ float g_c[K_NOISE];

// ---------------------------------------------------------------------------
// helpers
// ---------------------------------------------------------------------------
static __device__ __forceinline__ uint32_t smem_u32(const void* p) {
    uint32_t a;
    asm("{ .reg .u64 t; cvta.to.shared.u64 t, %1; cvt.u32.u64 %0, t; }"
        : "=r"(a) : "l"(p));
    return a;
}

static __device__ __forceinline__ void ldsm_x4(uint32_t* r, uint32_t addr) {
    asm volatile("ldmatrix.sync.aligned.m8n8.x4.shared.b16 {%0,%1,%2,%3}, [%4];"
                 : "=r"(r[0]), "=r"(r[1]), "=r"(r[2]), "=r"(r[3]) : "r"(addr));
}

static __device__ __forceinline__ void mma16816(float* d, const uint32_t* a,
                                                const uint32_t* b) {
    asm volatile(
        "mma.sync.aligned.m16n8k16.row.col.f32.bf16.bf16.f32 "
        "{%0,%1,%2,%3}, {%4,%5,%6,%7}, {%8,%9}, {%0,%1,%2,%3};"
        : "+f"(d[0]), "+f"(d[1]), "+f"(d[2]), "+f"(d[3])
        : "r"(a[0]), "r"(a[1]), "r"(a[2]), "r"(a[3]), "r"(b[0]), "r"(b[1]));
}

// softplus(x) = log(1 + e^x). Noise path lands in the polynomial branch
// (e^x ~ 1e-3) nearly always: 1 MUFU + 3 FMA.
__device__ __forceinline__ float softplus_f(float x)
{
    if (x > 8.0f) return x + __expf(-x);
    float z = __expf(x);
    if (z < 0.015625f) return z * fmaf(z, fmaf(z, 0.33333334f, -0.5f), 1.0f);
    return __logf(1.0f + z);
}

// ---------------------------------------------------------------------------
// Prep kernel: f32 -> bf16 conversion of input rows + gathered noise rows,
// written pre-swizzled (SW128, 128B rows) into 128-row tiles; per-noise
// constant; zero d_out. One task = one 16-byte output chunk.
// ---------------------------------------------------------------------------
__global__ void prep_kernel(const int* __restrict__ noise_samples,
                            const float* __restrict__ embs,
                            const float* __restrict__ input,
                            const float* __restrict__ logprob_noise,
                            float norm_c, float* __restrict__ d_out)
{
    int task = blockIdx.x * blockDim.x + threadIdx.x;
    if (task == 0) d_out[0] = 0.0f;

    const int total_in = ROWS_TOT * 8;        // 51200 input chunks
    const float* src;
    __nv_bfloat16* dstbase;
    int row, chunk;
    if (task < total_in) {
        row = task >> 3; chunk = task & 7;
        src = input + (size_t)row * DIM + chunk * 8;
        dstbase = g_in_bf16;
    } else {
        int t2 = task - total_in;
        if (t2 >= K_NOISE * 8) return;
        row = t2 >> 3; chunk = t2 & 7;
        int it = noise_samples[row];
        src = embs + (size_t)it * DIM + chunk * 8;
        dstbase = g_noise_bf16;
        if (chunk == 0) g_c[row] = norm_c + logprob_noise[it];
    }

    float4 a = ((const float4*)src)[0];
    float4 b = ((const float4*)src)[1];
    __nv_bfloat162 h0 = __floats2bfloat162_rn(a.x, a.y);
    __nv_bfloat162 h1 = __floats2bfloat162_rn(a.z, a.w);
    __nv_bfloat162 h2 = __floats2bfloat162_rn(b.x, b.y);
    __nv_bfloat162 h3 = __floats2bfloat162_rn(b.z, b.w);
    uint4 packed;
    packed.x = *(uint32_t*)&h0; packed.y = *(uint32_t*)&h1;
    packed.z = *(uint32_t*)&h2; packed.w = *(uint32_t*)&h3;

    uint32_t off = (uint32_t)(row & 127) * 128 + (uint32_t)chunk * 16;
    uint32_t sw  = SW128(off);
    char* dst = (char*)dstbase + (size_t)(row >> 7) * TILE_BYTES + sw;
    *(uint4*)dst = packed;
}

// ---------------------------------------------------------------------------
// Main kernel: one CTA = 128 rows x 128 noise via mma.sync bf16 (HMMA).
//   256 threads = 8 warps in a 4(M) x 2(N) grid; each warp: 32x64x64.
//   grid = (50 M-tiles, 8 N-tiles). Target term (f32 exact) in bn==0 blocks.
// ---------------------------------------------------------------------------
__global__ void __launch_bounds__(256)
nce_mma_kernel(const int* __restrict__ target,
               const float* __restrict__ input,
               const float* __restrict__ embs,
               const float* __restrict__ logprob_noise,
               float norm_c, float inv_rows, float* __restrict__ d_out)
{
    __shared__ __align__(1024) char s_a[TILE_BYTES];   // 16 KB A tile (bf16 SW128)
    __shared__ __align__(1024) char s_b[TILE_BYTES];   // 16 KB B tile (bf16 SW128)
    __shared__ float s_c[NT];
    __shared__ float s_red[8];

    const int tid    = threadIdx.x;
    const int lane   = tid & 31;
    const int wid    = tid >> 5;
    const int warp_m = wid & 3;        // 4 warps over M: 32 rows each
    const int warp_n = wid >> 2;       // 2 warps over N: 64 cols each
    const int bm     = blockIdx.x;
    const int bn     = blockIdx.y;

    // --- stage tiles: pre-swizzled in gmem -> straight 16B copies ---
    {
        const uint4* gA = (const uint4*)g_in_bf16    + (size_t)bm * (TILE_BYTES / 16);
        const uint4* gB = (const uint4*)g_noise_bf16 + (size_t)bn * (TILE_BYTES / 16);
        uint4* sA = (uint4*)s_a;
        uint4* sB = (uint4*)s_b;
#pragma unroll
        for (int i = 0; i < TILE_BYTES / 16 / 256; i++) {
            sA[i * 256 + tid] = gA[i * 256 + tid];
            sB[i * 256 + tid] = gB[i * 256 + tid];
        }
        if (tid < NT) s_c[tid] = g_c[bn * NT + tid];
    }

    // --- target term (exact f32), bn==0 only; before the barrier so its
    //     global loads overlap other warps' staging ---
    float local = 0.0f;
    if (bn == 0 && tid < MT) {
        int r = bm * MT + tid;
        int t = target[r];
        const float4* ti = (const float4*)(input + (size_t)r * DIM);
        const float4* te = (const float4*)(embs + (size_t)t * DIM);
        float acc = 0.0f;
#pragma unroll
        for (int i = 0; i < DIM / 4; i++) {
            float4 x = ti[i], e = te[i];
            acc = fmaf(x.x, e.x, fmaf(x.y, e.y, fmaf(x.z, e.z, fmaf(x.w, e.w, acc))));
        }
        float xt = acc - norm_c - logprob_noise[t];
        local += softplus_f(-xt);
    }
    __syncthreads();

    const uint32_t a_base = smem_u32(s_a);
    const uint32_t b_base = smem_u32(s_b);

    float acc[2][8][4] = {};   // [m16 tile][n8 tile][frag]

    // SW128 on 128B rows: sw(row*128 + chunk*16) = row*128 + ((chunk ^ (row&7))*16)
#pragma unroll
    for (int k = 0; k < 4; k++) {               // K = 4 x k16
        // A fragments: 2 x ldmatrix.x4 (m16k16 each)
        uint32_t afr[2][4];
#pragma unroll
        for (int mi = 0; mi < 2; mi++) {
            uint32_t row   = warp_m * 32 + mi * 16 + (lane & 15);
            uint32_t chunk = k * 2 + (lane >> 4);
            ldsm_x4(afr[mi], a_base + row * 128 + ((chunk ^ (row & 7)) << 4));
        }
        // B fragments: 4 x ldmatrix.x4, each serving two n8 tiles
        uint32_t bfr[8][2];
#pragma unroll
        for (int nj = 0; nj < 4; nj++) {
            uint32_t row   = warp_n * 64 + nj * 16 + (lane & 7) + ((lane >> 4) << 3);
            uint32_t chunk = k * 2 + ((lane >> 3) & 1);
            uint32_t b4[4];
            ldsm_x4(b4, b_base + row * 128 + ((chunk ^ (row & 7)) << 4));
            bfr[nj * 2][0] = b4[0]; bfr[nj * 2][1] = b4[1];
            bfr[nj * 2 + 1][0] = b4[2]; bfr[nj * 2 + 1][1] = b4[3];
        }
#pragma unroll
        for (int mi = 0; mi < 2; mi++)
#pragma unroll
            for (int ni = 0; ni < 8; ni++)
                mma16816(acc[mi][ni], afr[mi], bfr[ni]);
    }

    // --- epilogue: softplus of (score - c_k) on register accumulators ---
#pragma unroll
    for (int ni = 0; ni < 8; ni++) {
        int col = warp_n * 64 + ni * 8 + (lane & 3) * 2;
        float c0 = s_c[col], c1 = s_c[col + 1];
#pragma unroll
        for (int mi = 0; mi < 2; mi++) {
            local += softplus_f(acc[mi][ni][0] - c0);
            local += softplus_f(acc[mi][ni][1] - c1);
            local += softplus_f(acc[mi][ni][2] - c0);
            local += softplus_f(acc[mi][ni][3] - c1);
        }
    }

    // --- reduce block, one atomicAdd ---
#pragma unroll
    for (int o = 16; o; o >>= 1)
        local += __shfl_xor_sync(0xffffffffu, local, o);
    if (lane == 0) s_red[wid] = local;
    __syncthreads();
    if (tid == 0) {
        float s = 0.0f;
#pragma unroll
        for (int w = 0; w < 8; w++) s += s_red[w];
        atomicAdd(d_out, s * inv_rows);
    }
}

// ---------------------------------------------------------------------------
// Launch. Inputs (metadata order): target i32[6400], input f32[6400*64],
// embs f32[1e6*64], noise_samples i32[1024], logprob_noise f32[1e6].
// Output: f32[1] (mean loss).
// ---------------------------------------------------------------------------
extern "C" void kernel_launch(void* const* d_in, const int* in_sizes, int n_in,
                              void* d_out, int out_size)
{
    const int*   target = (const int*)d_in[0];
    const float* input  = (const float*)d_in[1];
    const float* embs   = (const float*)d_in[2];
    const int*   noise  = (const int*)d_in[3];
    const float* lpn    = (const float*)d_in[4];
    float*       out    = (float*)d_out;

    const int rows = in_sizes[0];                              // 6400
    const float norm_c = logf((float)in_sizes[4]) + logf((float)in_sizes[3]);

    const int prep_tasks = ROWS_TOT * 8 + K_NOISE * 8;         // 59392
    prep_kernel<<<(prep_tasks + 127) / 128, 128>>>(noise, embs, input, lpn, norm_c, out);

    dim3 grid(ROWS_TOT / MT, K_NOISE / NT);                    // 50 x 8
    nce_mma_kernel<<<grid, 256>>>(target, input, embs, lpn,
                                  norm_c, 1.0f / (float)rows, out);
}

// round 5
// speedup vs baseline: 2.8349x; 1.1214x over previous
#include <cuda_runtime.h>
#include <cuda_bf16.h>
#include <math.h>
#include <stdint.h>

// Shapes (fixed): B*N=6400 rows, K=1024 noise, D=64, V=1e6.
#define DIM        64
#define K_NOISE    1024
#define ROWS_TOT   6400
#define MT         128                 // M tile (rows per CTA)
#define NT         128                 // N tile (noise cols per CTA)
#define TILE_BYTES (128 * 128)         // 128 rows x 128B (64 bf16)

// ---------------------------------------------------------------------------
// helpers
// ---------------------------------------------------------------------------
static __device__ __forceinline__ uint32_t smem_u32(const void* p) {
    uint32_t a;
    asm("{ .reg .u64 t; cvta.to.shared.u64 t, %1; cvt.u32.u64 %0, t; }"
        : "=r"(a) : "l"(p));
    return a;
}

static __device__ __forceinline__ void ldsm_x4(uint32_t* r, uint32_t addr) {
    asm volatile("ldmatrix.sync.aligned.m8n8.x4.shared.b16 {%0,%1,%2,%3}, [%4];"
                 : "=r"(r[0]), "=r"(r[1]), "=r"(r[2]), "=r"(r[3]) : "r"(addr));
}

static __device__ __forceinline__ void mma16816(float* d, const uint32_t* a,
                                                const uint32_t* b) {
    asm volatile(
        "mma.sync.aligned.m16n8k16.row.col.f32.bf16.bf16.f32 "
        "{%0,%1,%2,%3}, {%4,%5,%6,%7}, {%8,%9}, {%0,%1,%2,%3};"
        : "+f"(d[0]), "+f"(d[1]), "+f"(d[2]), "+f"(d[3])
        : "r"(a[0]), "r"(a[1]), "r"(a[2]), "r"(a[3]), "r"(b[0]), "r"(b[1]));
}

// softplus(x) = log(1 + e^x). Noise scores land in the polynomial branch
// (e^x ~ 1e-3) essentially always: 1 MUFU + 3 FMA on the hot path.
__device__ __forceinline__ float softplus_f(float x)
{
    if (x > 8.0f) return x + __expf(-x);
    float z = __expf(x);
    if (z < 0.015625f) return z * fmaf(z, fmaf(z, 0.33333334f, -0.5f), 1.0f);
    return __logf(1.0f + z);
}

// convert 8 consecutive f32 -> 8 bf16 packed in a uint4
static __device__ __forceinline__ uint4 cvt8_bf16(const float* src)
{
    float4 a = ((const float4*)src)[0];
    float4 b = ((const float4*)src)[1];
    __nv_bfloat162 h0 = __floats2bfloat162_rn(a.x, a.y);
    __nv_bfloat162 h1 = __floats2bfloat162_rn(a.z, a.w);
    __nv_bfloat162 h2 = __floats2bfloat162_rn(b.x, b.y);
    __nv_bfloat162 h3 = __floats2bfloat162_rn(b.z, b.w);
    uint4 p;
    p.x = *(uint32_t*)&h0; p.y = *(uint32_t*)&h1;
    p.z = *(uint32_t*)&h2; p.w = *(uint32_t*)&h3;
    return p;
}

// ---------------------------------------------------------------------------
// Tiny init kernel: zero the scalar output (runs before main, stream-ordered).
// ---------------------------------------------------------------------------
__global__ void zero_kernel(float* __restrict__ d_out) { d_out[0] = 0.0f; }

// ---------------------------------------------------------------------------
// Fused NCE kernel: one CTA = 128 rows x 128 noise via mma.sync bf16.
//   Stages its own tiles: A rows converted f32->bf16, B noise rows gathered
//   from embs and converted, both written SW128-swizzled to smem.
//   8 warps in 4(M) x 2(N); each warp 32x64, processed as two 32-col passes
//   (halves accumulator registers -> 3 CTAs/SM).
// ---------------------------------------------------------------------------
__global__ void __launch_bounds__(256, 3)
nce_fused_kernel(const int* __restrict__ target,
                 const float* __restrict__ input,
                 const float* __restrict__ embs,
                 const int* __restrict__ noise_samples,
                 const float* __restrict__ logprob_noise,
                 float norm_c, float inv_rows, float* __restrict__ d_out)
{
    __shared__ __align__(1024) char s_a[TILE_BYTES];   // 16 KB A (bf16 SW128)
    __shared__ __align__(1024) char s_b[TILE_BYTES];   // 16 KB B (bf16 SW128)
    __shared__ float s_c[NT];
    __shared__ float s_red[8];

    const int tid    = threadIdx.x;
    const int lane   = tid & 31;
    const int wid    = tid >> 5;
    const int warp_m = wid & 3;        // 4 warps over M: 32 rows each
    const int warp_n = wid >> 2;       // 2 warps over N: 64 cols each
    const int bm     = blockIdx.x;
    const int bn     = blockIdx.y;

    // --- stage A: convert 128 input rows. 1024 chunks of 16B, 4 per thread ---
    // swizzle within a 128B row: chunk c at row r lands at ((c ^ (r&7)) << 4)
#pragma unroll
    for (int i = 0; i < 4; i++) {
        int flat = i * 256 + tid;            // 0..1023
        int row = flat >> 3, c = flat & 7;
        uint4 p = cvt8_bf16(input + (size_t)(bm * MT + row) * DIM + c * 8);
        *(uint4*)(s_a + row * 128 + ((c ^ (row & 7)) << 4)) = p;
    }
    // --- stage B: gather + convert 128 noise rows ---
#pragma unroll
    for (int i = 0; i < 4; i++) {
        int flat = i * 256 + tid;
        int row = flat >> 3, c = flat & 7;
        int it = noise_samples[bn * NT + row];        // L2/ctc hot
        uint4 p = cvt8_bf16(embs + (size_t)it * DIM + c * 8);
        *(uint4*)(s_b + row * 128 + ((c ^ (row & 7)) << 4)) = p;
    }
    if (tid < NT) {
        int it = noise_samples[bn * NT + tid];
        s_c[tid] = norm_c + logprob_noise[it];
    }

    // --- target term (exact f32), bn==0 only; overlaps staging ---
    float local = 0.0f;
    if (bn == 0 && tid < MT) {
        int r = bm * MT + tid;
        int t = target[r];
        const float4* ti = (const float4*)(input + (size_t)r * DIM);
        const float4* te = (const float4*)(embs + (size_t)t * DIM);
        float acc = 0.0f;
#pragma unroll
        for (int i = 0; i < DIM / 4; i++) {
            float4 x = ti[i], e = te[i];
            acc = fmaf(x.x, e.x, fmaf(x.y, e.y, fmaf(x.z, e.z, fmaf(x.w, e.w, acc))));
        }
        float xt = acc - norm_c - logprob_noise[t];
        local += softplus_f(-xt);
    }
    __syncthreads();

    const uint32_t a_base = smem_u32(s_a);
    const uint32_t b_base = smem_u32(s_b);

    // --- two 32-col passes per warp: acc regs 64 -> 32 ---
#pragma unroll
    for (int np = 0; np < 2; np++) {
        float acc[2][4][4] = {};
#pragma unroll
        for (int k = 0; k < 4; k++) {           // K = 4 x k16
            uint32_t afr[2][4];
#pragma unroll
            for (int mi = 0; mi < 2; mi++) {
                uint32_t row   = warp_m * 32 + mi * 16 + (lane & 15);
                uint32_t chunk = k * 2 + (lane >> 4);
                ldsm_x4(afr[mi], a_base + row * 128 + ((chunk ^ (row & 7)) << 4));
            }
            uint32_t bfr[4][2];
#pragma unroll
            for (int nj = 0; nj < 2; nj++) {
                uint32_t row = warp_n * 64 + np * 32 + nj * 16
                             + (lane & 7) + ((lane >> 4) << 3);
                uint32_t chunk = k * 2 + ((lane >> 3) & 1);
                uint32_t b4[4];
                ldsm_x4(b4, b_base + row * 128 + ((chunk ^ (row & 7)) << 4));
                bfr[nj * 2][0]     = b4[0]; bfr[nj * 2][1]     = b4[1];
                bfr[nj * 2 + 1][0] = b4[2]; bfr[nj * 2 + 1][1] = b4[3];
            }
#pragma unroll
            for (int mi = 0; mi < 2; mi++)
#pragma unroll
                for (int ni = 0; ni < 4; ni++)
                    mma16816(acc[mi][ni], afr[mi], bfr[ni]);
        }
        // epilogue for this 32-col pass
#pragma unroll
        for (int ni = 0; ni < 4; ni++) {
            int col = warp_n * 64 + np * 32 + ni * 8 + (lane & 3) * 2;
            float c0 = s_c[col], c1 = s_c[col + 1];
#pragma unroll
            for (int mi = 0; mi < 2; mi++) {
                local += softplus_f(acc[mi][ni][0] - c0);
                local += softplus_f(acc[mi][ni][1] - c1);
                local += softplus_f(acc[mi][ni][2] - c0);
                local += softplus_f(acc[mi][ni][3] - c1);
            }
        }
    }

    // --- reduce block, one atomicAdd ---
#pragma unroll
    for (int o = 16; o; o >>= 1)
        local += __shfl_xor_sync(0xffffffffu, local, o);
    if (lane == 0) s_red[wid] = local;
    __syncthreads();
    if (tid == 0) {
        float s = 0.0f;
#pragma unroll
        for (int w = 0; w < 8; w++) s += s_red[w];
        atomicAdd(d_out, s * inv_rows);
    }
}

// ---------------------------------------------------------------------------
// Launch. Inputs (metadata order): target i32[6400], input f32[6400*64],
// embs f32[1e6*64], noise_samples i32[1024], logprob_noise f32[1e6].
// Output: f32[1] (mean loss).
// ---------------------------------------------------------------------------
extern "C" void kernel_launch(void* const* d_in, const int* in_sizes, int n_in,
                              void* d_out, int out_size)
{
    const int*   target = (const int*)d_in[0];
    const float* input  = (const float*)d_in[1];
    const float* embs   = (const float*)d_in[2];
    const int*   noise  = (const int*)d_in[3];
    const float* lpn    = (const float*)d_in[4];
    float*       out    = (float*)d_out;

    const int rows = in_sizes[0];                              // 6400
    const float norm_c = logf((float)in_sizes[4]) + logf((float)in_sizes[3]);

    zero_kernel<<<1, 1>>>(out);
    dim3 grid(ROWS_TOT / MT, K_NOISE / NT);                    // 50 x 8
    nce_fused_kernel<<<grid, 256>>>(target, input, embs, noise, lpn,
                                    norm_c, 1.0f / (float)rows, out);
}